// round 1
// baseline (speedup 1.0000x reference)
#include <cuda_runtime.h>
#include <cstdint>

// ---------------- problem constants ----------------
#define BB   32
#define SS   256
#define TT   128
#define EENC 512
#define HH   512
#define EEMB 256
#define VV   32000
#define K0   1280   // emb(256)+context(512)+h0(512)
#define K1   1024   // h0(512)+h1(512)
#define KL   1024   // h1(512)+context(512)
#define OUT_TAIL_OFF 131072000ll // B*T*V

// ---------------- device scratch ----------------
__device__ float g_keyproj[BB*SS*HH];        // 16.8 MB
__device__ float g_Wcat0[2048*K0];           // 10.5 MB
__device__ float g_Wcat1[2048*K1];           // 8.4 MB
__device__ float g_bcat0[2048];
__device__ float g_bcat1[2048];
__device__ float g_xcat0[BB*K0];             // [emb | ctx | h0]
__device__ float g_xcat1[BB*K1];             // [h0 | h1]
__device__ float g_gates[BB*2048];
__device__ float g_h1[BB*HH];
__device__ float g_c0[BB*HH];
__device__ float g_c1[BB*HH];
__device__ float g_Xall[BB*TT*KL];           // 16.8 MB, row = b*T+t : [h1 | ctx]

// ---------------- math helpers ----------------
__device__ __forceinline__ float tanh_acc(float x){
    float xx = fminf(15.f, fmaxf(-15.f, x));
    float e  = __expf(2.f*xx);
    return 1.f - __fdividef(2.f, e + 1.f);
}
__device__ __forceinline__ float sigf(float x){
    float xx = fminf(30.f, fmaxf(-30.f, x));
    return __fdividef(1.f, 1.f + __expf(-xx));
}

// ---------------- init: build concat weights, zero state ----------------
__global__ void init_kernel(const float* __restrict__ Wih0, const float* __restrict__ Whh0,
                            const float* __restrict__ bih0, const float* __restrict__ bhh0,
                            const float* __restrict__ Wih1, const float* __restrict__ Whh1,
                            const float* __restrict__ bih1, const float* __restrict__ bhh1)
{
    const int NW0 = 2048*K0;          // 2,621,440
    const int NW1 = 2048*K1;          // 2,097,152
    const int NB  = 2048;
    const int NZ  = BB*HH*3 + BB*K0 + BB*K1; // h1,c0,c1 + xcat0 + xcat1
    const int TOT = NW0 + NW1 + 2*NB + NZ;
    for (int idx = blockIdx.x*blockDim.x + threadIdx.x; idx < TOT; idx += gridDim.x*blockDim.x){
        int r = idx;
        if (r < NW0){
            int j = r / K0, k = r % K0;
            g_Wcat0[r] = (k < 768) ? Wih0[j*768 + k] : Whh0[j*512 + (k-768)];
            continue;
        }
        r -= NW0;
        if (r < NW1){
            int j = r / K1, k = r % K1;
            g_Wcat1[r] = (k < 512) ? Wih1[j*512 + k] : Whh1[j*512 + (k-512)];
            continue;
        }
        r -= NW1;
        if (r < NB){ g_bcat0[r] = bih0[r] + bhh0[r]; continue; }
        r -= NB;
        if (r < NB){ g_bcat1[r] = bih1[r] + bhh1[r]; continue; }
        r -= NB;
        if (r < BB*HH){ g_h1[r] = 0.f; continue; }
        r -= BB*HH;
        if (r < BB*HH){ g_c0[r] = 0.f; continue; }
        r -= BB*HH;
        if (r < BB*HH){ g_c1[r] = 0.f; continue; }
        r -= BB*HH;
        if (r < BB*K0){ g_xcat0[r] = 0.f; continue; }
        r -= BB*K0;
        g_xcat1[r] = 0.f;
    }
}

// ---------------- generic TN GEMM: C[m][n] = sum_k A[m][k]*B[n][k] + bias[n] ----------------
template<int BM,int BN,int BK,int TM,int TN,int THREADS>
__global__ __launch_bounds__(THREADS) void gemm_tn(
    const float* __restrict__ A, const float* __restrict__ B,
    const float* __restrict__ bias, float* __restrict__ C,
    int M, int N, int K)
{
    constexpr int AF4 = BM*BK/(4*THREADS);
    constexpr int BF4 = BN*BK/(4*THREADS);
    constexpr int KC4 = BK/4;
    constexpr int NT  = BN/TN;
    static_assert((BM/TM)*(BN/TN) == THREADS, "thread shape");
    static_assert(AF4 >= 1 && BF4 >= 1, "load shape");

    __shared__ float As[2][BK][BM];
    __shared__ float Bs[2][BK][BN];

    const int tid = threadIdx.x;
    const int tm  = (tid / NT) * TM;
    const int tn  = (tid % NT) * TN;
    const size_t m0 = (size_t)blockIdx.y * BM;
    const size_t n0 = (size_t)blockIdx.x * BN;
    const float* Ab = A + m0 * K;
    const float* Bb = B + n0 * K;

    float acc[TM][TN];
#pragma unroll
    for (int i=0;i<TM;i++)
#pragma unroll
        for (int j=0;j<TN;j++) acc[i][j] = 0.f;

    float4 ra[AF4], rb[BF4];

    // prologue: load tile 0
#pragma unroll
    for (int i=0;i<AF4;i++){
        int f = tid + i*THREADS; int r = f/KC4, c = f%KC4;
        ra[i] = *reinterpret_cast<const float4*>(Ab + (size_t)r*K + c*4);
    }
#pragma unroll
    for (int i=0;i<BF4;i++){
        int f = tid + i*THREADS; int r = f/KC4, c = f%KC4;
        rb[i] = *reinterpret_cast<const float4*>(Bb + (size_t)r*K + c*4);
    }
#pragma unroll
    for (int i=0;i<AF4;i++){
        int f = tid + i*THREADS; int r = f/KC4, c = f%KC4;
        As[0][c*4+0][r]=ra[i].x; As[0][c*4+1][r]=ra[i].y;
        As[0][c*4+2][r]=ra[i].z; As[0][c*4+3][r]=ra[i].w;
    }
#pragma unroll
    for (int i=0;i<BF4;i++){
        int f = tid + i*THREADS; int r = f/KC4, c = f%KC4;
        Bs[0][c*4+0][r]=rb[i].x; Bs[0][c*4+1][r]=rb[i].y;
        Bs[0][c*4+2][r]=rb[i].z; Bs[0][c*4+3][r]=rb[i].w;
    }
    __syncthreads();

    const int KT = K / BK;
    for (int kt = 0; kt < KT; ++kt){
        const int cur = kt & 1;
        const bool nx = (kt + 1 < KT);
        if (nx){
            const float* Ab2 = Ab + (size_t)(kt+1)*BK;
            const float* Bb2 = Bb + (size_t)(kt+1)*BK;
#pragma unroll
            for (int i=0;i<AF4;i++){
                int f = tid + i*THREADS; int r = f/KC4, c = f%KC4;
                ra[i] = *reinterpret_cast<const float4*>(Ab2 + (size_t)r*K + c*4);
            }
#pragma unroll
            for (int i=0;i<BF4;i++){
                int f = tid + i*THREADS; int r = f/KC4, c = f%KC4;
                rb[i] = *reinterpret_cast<const float4*>(Bb2 + (size_t)r*K + c*4);
            }
        }
#pragma unroll
        for (int k=0;k<BK;k++){
            float a[TM], b[TN];
            if constexpr (TM % 4 == 0){
#pragma unroll
                for (int i=0;i<TM/4;i++){
                    float4 t = *reinterpret_cast<const float4*>(&As[cur][k][tm + i*4]);
                    a[i*4]=t.x; a[i*4+1]=t.y; a[i*4+2]=t.z; a[i*4+3]=t.w;
                }
            } else {
#pragma unroll
                for (int i=0;i<TM;i++) a[i] = As[cur][k][tm+i];
            }
            if constexpr (TN % 4 == 0){
#pragma unroll
                for (int j=0;j<TN/4;j++){
                    float4 t = *reinterpret_cast<const float4*>(&Bs[cur][k][tn + j*4]);
                    b[j*4]=t.x; b[j*4+1]=t.y; b[j*4+2]=t.z; b[j*4+3]=t.w;
                }
            } else {
#pragma unroll
                for (int j=0;j<TN;j++) b[j] = Bs[cur][k][tn+j];
            }
#pragma unroll
            for (int i=0;i<TM;i++)
#pragma unroll
                for (int j=0;j<TN;j++) acc[i][j] = fmaf(a[i], b[j], acc[i][j]);
        }
        if (nx){
            const int nb = cur ^ 1;
#pragma unroll
            for (int i=0;i<AF4;i++){
                int f = tid + i*THREADS; int r = f/KC4, c = f%KC4;
                As[nb][c*4+0][r]=ra[i].x; As[nb][c*4+1][r]=ra[i].y;
                As[nb][c*4+2][r]=ra[i].z; As[nb][c*4+3][r]=ra[i].w;
            }
#pragma unroll
            for (int i=0;i<BF4;i++){
                int f = tid + i*THREADS; int r = f/KC4, c = f%KC4;
                Bs[nb][c*4+0][r]=rb[i].x; Bs[nb][c*4+1][r]=rb[i].y;
                Bs[nb][c*4+2][r]=rb[i].z; Bs[nb][c*4+3][r]=rb[i].w;
            }
            __syncthreads();
        }
    }
    // epilogue
#pragma unroll
    for (int i=0;i<TM;i++){
#pragma unroll
        for (int j=0;j<TN;j++){
            size_t cn = n0 + tn + j;
            C[(m0 + tm + i)*(size_t)N + cn] = acc[i][j] + bias[cn];
        }
    }
}

// ---------------- attention + emb gather (one block per batch) ----------------
__global__ __launch_bounds__(256) void attn_kernel(
    const float* __restrict__ enc, const int* __restrict__ tok,
    const float* __restrict__ emb, const float* __restrict__ Wq,
    const float* __restrict__ bq,  const float* __restrict__ v, int t)
{
    const int b = blockIdx.x, tid = threadIdx.x;
    const int w = tid >> 5, lane = tid & 31;
    __shared__ float h1s[HH], qp[HH], vs[HH], sc[SS];
    __shared__ float red[8];
    __shared__ float smax_s, sinv_s;

    for (int i = tid; i < HH; i += 256){ h1s[i] = g_h1[b*HH + i]; vs[i] = v[i]; }
    __syncthreads();

    // qproj[h] = bq[h] + sum_k Wq[h][k]*h1[k]  (warp per 64 outputs)
    for (int hh = 0; hh < 64; ++hh){
        int h = w*64 + hh;
        const float* wr = Wq + (size_t)h*HH;
        float p = 0.f;
#pragma unroll
        for (int i = 0; i < 16; i++) p = fmaf(wr[i*32 + lane], h1s[i*32 + lane], p);
#pragma unroll
        for (int o = 16; o; o >>= 1) p += __shfl_xor_sync(0xffffffffu, p, o);
        if (lane == 0) qp[h] = p + bq[h];
    }
    // emb gather into xcat0[:, 0:256]
    {
        int row = tok[b*TT + t];
        if (tid < 256) g_xcat0[b*K0 + tid] = emb[(size_t)row*EEMB + tid];
    }
    __syncthreads();

    // scores[s] = sum_h v[h]*tanh(kp[b,s,h] + qp[h])
    {
        const int s = tid;
        const float* kp = g_keyproj + ((size_t)(b*SS + s))*HH;
        float acc = 0.f;
#pragma unroll 2
        for (int h = 0; h < HH; h += 4){
            float4 k4 = *reinterpret_cast<const float4*>(kp + h);
            acc = fmaf(vs[h+0], tanh_acc(k4.x + qp[h+0]), acc);
            acc = fmaf(vs[h+1], tanh_acc(k4.y + qp[h+1]), acc);
            acc = fmaf(vs[h+2], tanh_acc(k4.z + qp[h+2]), acc);
            acc = fmaf(vs[h+3], tanh_acc(k4.w + qp[h+3]), acc);
        }
        sc[s] = acc;
    }
    __syncthreads();

    // softmax over 256
    float x = sc[tid];
    float m = x;
#pragma unroll
    for (int o = 16; o; o >>= 1) m = fmaxf(m, __shfl_xor_sync(0xffffffffu, m, o));
    if (lane == 0) red[w] = m;
    __syncthreads();
    if (tid == 0){
        float mm = red[0];
#pragma unroll
        for (int i = 1; i < 8; i++) mm = fmaxf(mm, red[i]);
        smax_s = mm;
    }
    __syncthreads();
    float ex = __expf(x - smax_s);
    float s2 = ex;
#pragma unroll
    for (int o = 16; o; o >>= 1) s2 += __shfl_xor_sync(0xffffffffu, s2, o);
    if (lane == 0) red[w] = s2;
    __syncthreads();
    if (tid == 0){
        float ss = 0.f;
#pragma unroll
        for (int i = 0; i < 8; i++) ss += red[i];
        sinv_s = 1.f / ss;
    }
    __syncthreads();
    sc[tid] = ex * sinv_s;
    __syncthreads();

    // context[e] = sum_s w[s]*enc[b,s,e]  -> xcat0[:,256:768] and Xall[:,512:1024]
    for (int e0 = tid; e0 < EENC; e0 += 256){
        float acc = 0.f;
        const float* eb = enc + ((size_t)b*SS)*EENC + e0;
#pragma unroll 4
        for (int s = 0; s < SS; s++) acc = fmaf(sc[s], eb[(size_t)s*EENC], acc);
        g_xcat0[b*K0 + 256 + e0] = acc;
        g_Xall[((size_t)(b*TT + t))*KL + 512 + e0] = acc;
    }
}

// ---------------- LSTM cell elementwise ----------------
__global__ __launch_bounds__(512) void cell0_kernel()
{
    const int b = blockIdx.x, u = threadIdx.x;
    const float* g = g_gates + b*2048;
    float gi = g[u], gf = g[512+u], gg = g[1024+u], go = g[1536+u];
    float c = sigf(gf)*g_c0[b*HH + u] + sigf(gi)*tanh_acc(gg);
    float h = sigf(go)*tanh_acc(c);
    g_c0[b*HH + u] = c;
    g_xcat0[b*K0 + 768 + u] = h;   // h0 for next step's gates0
    g_xcat1[b*K1 + u]       = h;   // h0 input to gates1 (this step)
}

__global__ __launch_bounds__(512) void cell1_kernel(int t)
{
    const int b = blockIdx.x, u = threadIdx.x;
    const float* g = g_gates + b*2048;
    float gi = g[u], gf = g[512+u], gg = g[1024+u], go = g[1536+u];
    float c = sigf(gf)*g_c1[b*HH + u] + sigf(gi)*tanh_acc(gg);
    float h = sigf(go)*tanh_acc(c);
    g_c1[b*HH + u] = c;
    g_h1[b*HH + u] = h;                       // query for next step's attention
    g_xcat1[b*K1 + 512 + u] = h;              // h1 input to next step's gates1
    g_Xall[((size_t)(b*TT + t))*KL + u] = h;  // logits input row
}

// ---------------- tail: final h,c states ----------------
__global__ __launch_bounds__(512) void tail_kernel(float* __restrict__ out)
{
    int idx = blockIdx.x*blockDim.x + threadIdx.x;   // 65536 total
    int part = idx / (BB*HH);
    int off  = idx % (BB*HH);
    int b = off / HH, u = off % HH;
    float val;
    if      (part == 0) val = g_xcat1[b*K1 + u];   // h0 final
    else if (part == 1) val = g_h1[off];           // h1 final
    else if (part == 2) val = g_c0[off];           // c0 final
    else                val = g_c1[off];           // c1 final
    out[OUT_TAIL_OFF + idx] = val;
}

// ---------------- launch ----------------
extern "C" void kernel_launch(void* const* d_in, const int* in_sizes, int n_in,
                              void* d_out, int out_size)
{
    const float* enc  = (const float*)d_in[0];
    const int*   tok  = (const int*)  d_in[1];
    const float* emb  = (const float*)d_in[2];
    const float* Wq   = (const float*)d_in[3];
    const float* bq   = (const float*)d_in[4];
    const float* Wk   = (const float*)d_in[5];
    const float* bk   = (const float*)d_in[6];
    const float* v    = (const float*)d_in[7];
    const float* Wih0 = (const float*)d_in[8];
    const float* Whh0 = (const float*)d_in[9];
    const float* bih0 = (const float*)d_in[10];
    const float* bhh0 = (const float*)d_in[11];
    const float* Wih1 = (const float*)d_in[12];
    const float* Whh1 = (const float*)d_in[13];
    const float* bih1 = (const float*)d_in[14];
    const float* bhh1 = (const float*)d_in[15];
    const float* Wout = (const float*)d_in[16];
    const float* bout = (const float*)d_in[17];
    float* out = (float*)d_out;

    float *p_keyproj, *p_Wcat0, *p_bcat0, *p_Wcat1, *p_bcat1;
    float *p_xcat0, *p_xcat1, *p_gates, *p_Xall;
    cudaGetSymbolAddress((void**)&p_keyproj, g_keyproj);
    cudaGetSymbolAddress((void**)&p_Wcat0,  g_Wcat0);
    cudaGetSymbolAddress((void**)&p_bcat0,  g_bcat0);
    cudaGetSymbolAddress((void**)&p_Wcat1,  g_Wcat1);
    cudaGetSymbolAddress((void**)&p_bcat1,  g_bcat1);
    cudaGetSymbolAddress((void**)&p_xcat0,  g_xcat0);
    cudaGetSymbolAddress((void**)&p_xcat1,  g_xcat1);
    cudaGetSymbolAddress((void**)&p_gates,  g_gates);
    cudaGetSymbolAddress((void**)&p_Xall,   g_Xall);

    // init concat weights + zero state
    init_kernel<<<2048, 256>>>(Wih0, Whh0, bih0, bhh0, Wih1, Whh1, bih1, bhh1);

    // key_proj = enc(8192x512) @ Wk^T(512x512) + bk
    {
        dim3 grid(HH/64, (BB*SS)/64);
        gemm_tn<64,64,16,4,4,256><<<grid, 256>>>(enc, Wk, bk, p_keyproj, BB*SS, HH, EENC);
    }

    // sequential decode: recurrence only (logits deferred)
    for (int t = 0; t < TT; ++t){
        attn_kernel<<<BB, 256>>>(enc, tok, emb, Wq, bq, v, t);
        {
            dim3 grid(2048/16, 1);
            gemm_tn<32,16,32,2,2,128><<<grid, 128>>>(p_xcat0, p_Wcat0, p_bcat0, p_gates, BB, 2048, K0);
        }
        cell0_kernel<<<BB, 512>>>();
        {
            dim3 grid(2048/16, 1);
            gemm_tn<32,16,32,2,2,128><<<grid, 128>>>(p_xcat1, p_Wcat1, p_bcat1, p_gates, BB, 2048, K1);
        }
        cell1_kernel<<<BB, 512>>>(t);
    }

    // phase 2: all logits at once: Xall(4096x1024) @ Wout^T(32000x1024) + bout -> out
    {
        dim3 grid(VV/64, (BB*TT)/128);
        gemm_tn<128,64,16,8,8,128><<<grid, 128>>>(p_Xall, Wout, bout, out, BB*TT, VV, KL);
    }

    // final h, c
    tail_kernel<<<128, 512>>>(out);
}